// round 1
// baseline (speedup 1.0000x reference)
#include <cuda_runtime.h>
#include <math.h>

// Problem constants (fixed by the dataset)
#define NVOX 200000
#define CH   128
#define MT   64        // voxels per block tile  (NVOX % MT == 0 -> 3125 blocks)
#define CONV_THREADS 128

// Scratch (device globals; no allocation allowed)
__device__ float g_x [NVOX * 8];     // [feat, sin0..2, cos0..2, 0]
__device__ float g_h1[NVOX * CH];
__device__ float g_h2[NVOX * CH];
__device__ float g_h3[NVOX * CH];

typedef unsigned long long ull;

__device__ __forceinline__ ull pack2(float x) {
    ull r; asm("mov.b64 %0, {%1, %1};" : "=l"(r) : "f"(x)); return r;
}
__device__ __forceinline__ void ffma2(ull &d, ull a, ull b) {
    // packed fp32x2 FMA: d.lo += a.lo*b.lo ; d.hi += a.hi*b.hi  (exact fp32 FMA per lane)
    asm("fma.rn.f32x2 %0, %1, %2, %0;" : "+l"(d) : "l"(a), "l"(b));
}
__device__ __forceinline__ float2 unpack2(ull v) {
    float2 r; asm("mov.b64 {%0, %1}, %2;" : "=f"(r.x), "=f"(r.y) : "l"(v)); return r;
}
__device__ __forceinline__ float silu(float v) { return v / (1.0f + expf(-v)); }

// ---------------------------------------------------------------------------
// Embedding: x = [feat, sin(t*pi), sin(t*2pi), sin(t*4pi), cos(...) x3, 0]
// ---------------------------------------------------------------------------
__global__ void embed_kernel(const float* __restrict__ feat,
                             const int*   __restrict__ t,
                             float* __restrict__ gx)
{
    int i = blockIdx.x * blockDim.x + threadIdx.x;
    if (i >= NVOX) return;
    const float PI_F = 3.14159265358979323846f;   // rounds to fl(pi) = jnp.pi f32
    float tv = (float)t[i];
    float a0 = tv * PI_F;
    float a1 = tv * (2.0f * PI_F);
    float a2 = tv * (4.0f * PI_F);
    float* row = gx + (size_t)i * 8;
    row[0] = feat[i];
    row[1] = sinf(a0); row[2] = sinf(a1); row[3] = sinf(a2);
    row[4] = cosf(a0); row[5] = cosf(a1); row[6] = cosf(a2);
    row[7] = 0.0f;
}

// ---------------------------------------------------------------------------
// Generic gathered conv layer:
//   out[i,c] = silu( bias[c] + sum_k sum_j xin[nidx[k,i], j] * W[k, j, c] )
// CIN   : padded input stride / smem K dim (8 or 128)
// CIN_W : actual rows in W (7 or 128) — rows >= CIN_W are zero-padded in smem
// Tile: 64 voxels x 128 couts, 128 threads, per-thread 8m x 8c register tile,
// inner loop in fma.rn.f32x2 (2 MACs/instr).
// ---------------------------------------------------------------------------
template<int CIN, int CIN_W, int NK, bool GATHER>
__global__ void __launch_bounds__(CONV_THREADS, 2)
conv_kernel(const float* __restrict__ xin,
            const int*   __restrict__ nidx,
            const float* __restrict__ W,
            const float* __restrict__ bias,
            float* __restrict__ out)
{
    extern __shared__ float smem[];
    float* Ws = smem;                       // [CIN][128]
    float* Xt = smem + CIN * 128;           // [CIN][68]  (pad 64->68 keeps f4 align, kills conflicts)

    const int tid  = threadIdx.x;
    const int base = blockIdx.x * MT;
    const int cg = tid & 15;                // 16 cout groups
    const int mg = tid >> 4;                // 8 m groups
    const int c0 = cg * 4;
    const int c1 = cg * 4 + 64;
    const int m0 = mg * 8;

    const int r    = tid >> 1;              // gather: 2 threads per row
    const int half = tid & 1;
    constexpr int F4H = (CIN / 4) / 2;      // float4 per row per thread

    ull acc[8][4];
    #pragma unroll
    for (int a = 0; a < 8; a++)
        #pragma unroll
        for (int b = 0; b < 4; b++) acc[a][b] = 0ull;

    for (int k = 0; k < NK; k++) {
        __syncthreads();   // previous tile fully consumed

        // --- stage W[k] into smem (zero-pad rows >= CIN_W) ---
        const float4* Wk = (const float4*)(W + (size_t)k * CIN_W * 128);
        #pragma unroll
        for (int idx = tid; idx < CIN * 32; idx += CONV_THREADS) {
            int j = idx >> 5;
            float4 v = (j < CIN_W) ? Wk[(size_t)j * 32 + (idx & 31)]
                                   : make_float4(0.f, 0.f, 0.f, 0.f);
            ((float4*)Ws)[idx] = v;
        }

        // --- gather 64 rows (sentinel NVOX -> zeros), store transposed ---
        int row_idx;
        if (GATHER) row_idx = nidx[(size_t)k * NVOX + base + r];
        else        row_idx = base + r;
        bool ok = (row_idx < NVOX);
        const float4* src = (const float4*)(xin + (size_t)(ok ? row_idx : 0) * CIN);
        #pragma unroll
        for (int q = 0; q < F4H; q++) {
            int j4 = half * F4H + q;
            float4 v = ok ? src[j4] : make_float4(0.f, 0.f, 0.f, 0.f);
            int j = j4 * 4;
            Xt[(j + 0) * 68 + r] = v.x;
            Xt[(j + 1) * 68 + r] = v.y;
            Xt[(j + 2) * 68 + r] = v.z;
            Xt[(j + 3) * 68 + r] = v.w;
        }
        __syncthreads();

        // --- compute: per j, 3x LDS.128 feeds 32 FFMA2 (64 MACs) ---
        #pragma unroll 4
        for (int j = 0; j < CIN; j++) {
            float4 xa = *(const float4*)(Xt + j * 68 + m0);
            float4 xb = *(const float4*)(Xt + j * 68 + m0 + 4);
            ulonglong2 wa = *(const ulonglong2*)(Ws + j * 128 + c0);
            ulonglong2 wb = *(const ulonglong2*)(Ws + j * 128 + c1);
            float xm[8] = {xa.x, xa.y, xa.z, xa.w, xb.x, xb.y, xb.z, xb.w};
            #pragma unroll
            for (int mi = 0; mi < 8; mi++) {
                ull xd = pack2(xm[mi]);
                ffma2(acc[mi][0], xd, wa.x);
                ffma2(acc[mi][1], xd, wa.y);
                ffma2(acc[mi][2], xd, wb.x);
                ffma2(acc[mi][3], xd, wb.y);
            }
        }
    }

    // --- epilogue: bias + silu, vectorized stores ---
    float4 ba = *(const float4*)(bias + c0);
    float4 bb = *(const float4*)(bias + c1);
    #pragma unroll
    for (int mi = 0; mi < 8; mi++) {
        float2 p0 = unpack2(acc[mi][0]);
        float2 p1 = unpack2(acc[mi][1]);
        float2 p2 = unpack2(acc[mi][2]);
        float2 p3 = unpack2(acc[mi][3]);
        float4 va, vb;
        va.x = silu(p0.x + ba.x); va.y = silu(p0.y + ba.y);
        va.z = silu(p1.x + ba.z); va.w = silu(p1.y + ba.w);
        vb.x = silu(p2.x + bb.x); vb.y = silu(p2.y + bb.y);
        vb.z = silu(p3.x + bb.z); vb.w = silu(p3.y + bb.w);
        float* orow = out + (size_t)(base + m0 + mi) * CH;
        *(float4*)(orow + c0) = va;
        *(float4*)(orow + c1) = vb;
    }
}

// ---------------------------------------------------------------------------
// Final 1x1 conv to 1 channel: out[i] = b4 + dot(h3[i,:], W4[:,0])
// ---------------------------------------------------------------------------
__global__ void out_kernel(const float* __restrict__ h3,
                           const float* __restrict__ W4,
                           const float* __restrict__ b4,
                           float* __restrict__ out)
{
    int g    = blockIdx.x * blockDim.x + threadIdx.x;
    int warp = g >> 5;
    int lane = g & 31;
    if (warp >= NVOX) return;
    float4 h = *(const float4*)(h3 + (size_t)warp * CH + lane * 4);
    float4 w = *(const float4*)(W4 + lane * 4);
    float s = h.x * w.x + h.y * w.y + h.z * w.z + h.w * w.w;
    #pragma unroll
    for (int off = 16; off; off >>= 1) s += __shfl_xor_sync(0xffffffffu, s, off);
    if (lane == 0) out[warp] = s + b4[0];
}

// ---------------------------------------------------------------------------
extern "C" void kernel_launch(void* const* d_in, const int* in_sizes, int n_in,
                              void* d_out, int out_size)
{
    const float* feat = (const float*)d_in[0];
    const int*   t    = (const int*)  d_in[1];
    const int*   nidx = (const int*)  d_in[2];
    const float* W1   = (const float*)d_in[3];
    const float* b1   = (const float*)d_in[4];
    const float* W2   = (const float*)d_in[5];
    const float* b2   = (const float*)d_in[6];
    const float* W3   = (const float*)d_in[7];
    const float* b3   = (const float*)d_in[8];
    const float* W4   = (const float*)d_in[9];
    const float* b4   = (const float*)d_in[10];
    float* out = (float*)d_out;

    float *px, *ph1, *ph2, *ph3;
    cudaGetSymbolAddress((void**)&px,  g_x);
    cudaGetSymbolAddress((void**)&ph1, g_h1);
    cudaGetSymbolAddress((void**)&ph2, g_h2);
    cudaGetSymbolAddress((void**)&ph3, g_h3);

    const int smem_big   = (128 * 128 + 128 * 68) * 4;   // 100,352 B
    const int smem_small = (8   * 128 + 8   * 68) * 4;   //   6,272 B
    cudaFuncSetAttribute(conv_kernel<128, 128, 27, true>,
                         cudaFuncAttributeMaxDynamicSharedMemorySize, smem_big);
    cudaFuncSetAttribute(conv_kernel<128, 128, 1, false>,
                         cudaFuncAttributeMaxDynamicSharedMemorySize, smem_big);

    embed_kernel<<<(NVOX + 255) / 256, 256>>>(feat, t, px);
    conv_kernel<8,   7,   27, true ><<<NVOX / MT, CONV_THREADS, smem_small>>>(px,  nidx, W1, b1, ph1);
    conv_kernel<128, 128, 27, true ><<<NVOX / MT, CONV_THREADS, smem_big  >>>(ph1, nidx, W2, b2, ph2);
    conv_kernel<128, 128, 1,  false><<<NVOX / MT, CONV_THREADS, smem_big  >>>(ph2, nullptr, W3, b3, ph3);
    out_kernel<<<(NVOX * 32 + 255) / 256, 256>>>(ph3, W4, b4, out);
}

// round 3
// speedup vs baseline: 1.4659x; 1.4659x over previous
#include <cuda_runtime.h>
#include <cuda_bf16.h>
#include <math.h>
#include <stdint.h>

#define NVOX 200000
#define CH   128
#define MT   128                           // voxels per CTA tile
#define NT   ((NVOX + MT - 1) / MT)        // 1563 CTAs
#define NTHREADS 256

// ---------------------------------------------------------------------------
// Device scratch
// ---------------------------------------------------------------------------
__device__ __nv_bfloat16 g_x_hi[(size_t)NVOX * 16];
__device__ __nv_bfloat16 g_x_lo[(size_t)NVOX * 16];
__device__ __nv_bfloat16 g_h1_hi[(size_t)NVOX * CH];
__device__ __nv_bfloat16 g_h1_lo[(size_t)NVOX * CH];
__device__ __nv_bfloat16 g_h2_hi[(size_t)NVOX * CH];
__device__ __nv_bfloat16 g_h2_lo[(size_t)NVOX * CH];
__device__ __nv_bfloat16 g_w1_hi[27 * 128 * 16];   // [k][cout][j pad16]
__device__ __nv_bfloat16 g_w1_lo[27 * 128 * 16];
__device__ __nv_bfloat16 g_w2_hi[27 * 128 * 128];  // [k][cout][j]
__device__ __nv_bfloat16 g_w2_lo[27 * 128 * 128];
__device__ __nv_bfloat16 g_w3_hi[128 * 128];       // [cout][j]
__device__ __nv_bfloat16 g_w3_lo[128 * 128];

// ---------------------------------------------------------------------------
// Portable PTX helpers (all legal at compute_103)
// ---------------------------------------------------------------------------
__device__ __forceinline__ uint32_t smem_u32(const void* p) {
    uint32_t a;
    asm("{ .reg .u64 t; cvta.to.shared.u64 t, %1; cvt.u32.u64 %0, t; }" : "=r"(a) : "l"(p));
    return a;
}
__device__ __forceinline__ void cp16(uint32_t dst, const void* src, uint32_t sz) {
    asm volatile("cp.async.cg.shared.global [%0], [%1], 16, %2;"
                 :: "r"(dst), "l"(src), "r"(sz) : "memory");
}
__device__ __forceinline__ void cp_commit() {
    asm volatile("cp.async.commit_group;" ::: "memory");
}
template<int N> __device__ __forceinline__ void cp_wait() {
    asm volatile("cp.async.wait_group %0;" :: "n"(N) : "memory");
}
__device__ __forceinline__ void ldsm4(uint32_t* r, uint32_t a) {
    asm volatile("ldmatrix.sync.aligned.m8n8.x4.shared.b16 {%0,%1,%2,%3}, [%4];"
                 : "=r"(r[0]), "=r"(r[1]), "=r"(r[2]), "=r"(r[3]) : "r"(a));
}
__device__ __forceinline__ void mma16816(float* c, const uint32_t* a, const uint32_t* b) {
    asm volatile(
        "mma.sync.aligned.m16n8k16.row.col.f32.bf16.bf16.f32 "
        "{%0,%1,%2,%3}, {%4,%5,%6,%7}, {%8,%9}, {%0,%1,%2,%3};"
        : "+f"(c[0]), "+f"(c[1]), "+f"(c[2]), "+f"(c[3])
        : "r"(a[0]), "r"(a[1]), "r"(a[2]), "r"(a[3]), "r"(b[0]), "r"(b[1]));
}
__device__ __forceinline__ float silu_f(float v) { return v / (1.f + __expf(-v)); }

// ---------------------------------------------------------------------------
// Embedding -> bf16 hi/lo, 16-wide padded rows
// ---------------------------------------------------------------------------
__global__ void embed_k(const float* __restrict__ feat, const int* __restrict__ t,
                        __nv_bfloat16* __restrict__ xh, __nv_bfloat16* __restrict__ xl)
{
    int i = blockIdx.x * blockDim.x + threadIdx.x;
    if (i >= NVOX) return;
    const float PI_F = 3.14159265358979323846f;
    float tv = (float)t[i];
    float vals[7];
    vals[0] = feat[i];
    vals[1] = sinf(tv * PI_F);
    vals[2] = sinf(tv * (2.f * PI_F));
    vals[3] = sinf(tv * (4.f * PI_F));
    vals[4] = cosf(tv * PI_F);
    vals[5] = cosf(tv * (2.f * PI_F));
    vals[6] = cosf(tv * (4.f * PI_F));
    #pragma unroll
    for (int j = 0; j < 16; j++) {
        float v = (j < 7) ? vals[j] : 0.f;
        __nv_bfloat16 h = __float2bfloat16_rn(v);
        xh[(size_t)i * 16 + j] = h;
        xl[(size_t)i * 16 + j] = __float2bfloat16_rn(v - __bfloat162float(h));
    }
}

// Weight prep: transpose to [.. , cout, j] and split fp32 -> bf16 hi/lo
__global__ void prep_w1_k(const float* __restrict__ W1,
                          __nv_bfloat16* __restrict__ wh, __nv_bfloat16* __restrict__ wl)
{
    int idx = blockIdx.x * blockDim.x + threadIdx.x;
    if (idx >= 27 * 128 * 16) return;
    int j = idx & 15, c = (idx >> 4) & 127, k = idx >> 11;
    float v = (j < 7) ? W1[((size_t)k * 7 + j) * 128 + c] : 0.f;
    __nv_bfloat16 h = __float2bfloat16_rn(v);
    wh[idx] = h;
    wl[idx] = __float2bfloat16_rn(v - __bfloat162float(h));
}
__global__ void prep_w2_k(const float* __restrict__ W2,
                          __nv_bfloat16* __restrict__ wh, __nv_bfloat16* __restrict__ wl)
{
    int idx = blockIdx.x * blockDim.x + threadIdx.x;
    if (idx >= 27 * 128 * 128) return;
    int j = idx & 127, c = (idx >> 7) & 127, k = idx >> 14;
    float v = W2[((size_t)k * 128 + j) * 128 + c];
    __nv_bfloat16 h = __float2bfloat16_rn(v);
    wh[idx] = h;
    wl[idx] = __float2bfloat16_rn(v - __bfloat162float(h));
}
__global__ void prep_w3_k(const float* __restrict__ W3,
                          __nv_bfloat16* __restrict__ wh, __nv_bfloat16* __restrict__ wl)
{
    int idx = blockIdx.x * blockDim.x + threadIdx.x;
    if (idx >= 128 * 128) return;
    int j = idx & 127, c = idx >> 7;
    float v = W3[(size_t)j * 128 + c];
    __nv_bfloat16 h = __float2bfloat16_rn(v);
    wh[idx] = h;
    wl[idx] = __float2bfloat16_rn(v - __bfloat162float(h));
}

// ---------------------------------------------------------------------------
// Gathered conv layer: mma.sync bf16, 3-term split, fp32 accum.
//  CIN: input channels (16 or 128). CHUNKS = CIN/8 16B chunks per row.
//  EPI 0: silu -> bf16 hi/lo store.  EPI 1: fused silu -> dot(W4) + b4 -> float.
// Tile: 128 voxels x 128 couts, 8 warps (4x2), warp tile 32x64.
// ---------------------------------------------------------------------------
template<int CIN, int NK, bool GATHER, int EPI>
__global__ void __launch_bounds__(NTHREADS)
conv_mma(const __nv_bfloat16* __restrict__ xhi, const __nv_bfloat16* __restrict__ xlo,
         const int* __restrict__ nidx,
         const __nv_bfloat16* __restrict__ whi, const __nv_bfloat16* __restrict__ wlo,
         const float* __restrict__ bias,
         const float* __restrict__ w4, const float* __restrict__ b4,
         __nv_bfloat16* __restrict__ ohi, __nv_bfloat16* __restrict__ olo,
         float* __restrict__ ofl)
{
    constexpr int CHUNKS = CIN / 8;           // 16B chunks per row
    constexpr int SWZ    = (CHUNKS >= 8) ? 7 : (CHUNKS - 1);
    constexpr int RB     = CHUNKS * 16;       // row bytes
    constexpr int TB     = 128 * RB;          // tile bytes
    constexpr int KSTEPS = CIN / 16;
    constexpr uint32_t HDR = 2048;

    extern __shared__ char smem[];
    const uint32_t sb = smem_u32(smem);
    float* bias_s = (float*)smem;             // [128]
    float* w4_s   = (float*)(smem + 512);     // [128]
    float* red    = (float*)(smem + 1024);    // [2][128]

    const int tid  = threadIdx.x;
    const int wid  = tid >> 5, lane = tid & 31;
    const int wm   = wid >> 1, wn = wid & 1;  // warp grid 4x2
    const int g    = lane >> 2, tig = lane & 3;
    const int base = blockIdx.x * MT;

    const uint32_t sW = sb + HDR;                       // W hi tile (lo at +TB)
    const uint32_t sA = sb + HDR + 2 * TB;              // A[buf][half] tiles

    if (tid < 128) {
        bias_s[tid] = bias[tid];
        if (EPI == 1) { w4_s[tid] = w4[tid]; red[tid] = 0.f; red[128 + tid] = 0.f; }
    }

    // gather-thread mapping: half = hi/lo, r = row within tile
    const int half = tid & 1, r = tid >> 1;
    const __nv_bfloat16* xsrc = half ? xlo : xhi;
    const __nv_bfloat16* wsrc = half ? wlo : whi;

    // ---- prologue: issue A(0) ----
    {
        int i = base + r;
        int ridx;
        if (GATHER) ridx = (i < NVOX) ? nidx[(size_t)0 * NVOX + i] : NVOX;
        else        ridx = i;
        bool ok = (ridx < NVOX);
        const char* src = (const char*)(xsrc + (size_t)(ok ? ridx : 0) * CIN);
        uint32_t dst = sA + half * TB + r * RB;
        #pragma unroll
        for (int c = 0; c < CHUNKS; c++)
            cp16(dst + ((c ^ (r & SWZ)) << 4), src + c * 16, ok ? 16u : 0u);
    }
    cp_commit();

    float acc[2][8][4];
    #pragma unroll
    for (int a = 0; a < 2; a++)
        #pragma unroll
        for (int b = 0; b < 8; b++)
            #pragma unroll
            for (int q = 0; q < 4; q++) acc[a][b][q] = 0.f;

    int buf = 0;
    for (int k = 0; k < NK; k++) {
        __syncthreads();   // W buffer free (prev compute done); header staged

        // ---- issue W(k) (own group) ----
        {
            const char* src = (const char*)(wsrc + ((size_t)k * 128 + r) * CIN);
            uint32_t dst = sW + half * TB + r * RB;
            #pragma unroll
            for (int c = 0; c < CHUNKS; c++)
                cp16(dst + ((c ^ (r & SWZ)) << 4), src + c * 16, 16u);
        }
        cp_commit();

        // ---- issue A(k+1) (own group) ----
        if (k + 1 < NK) {
            int i = base + r;
            int ridx;
            if (GATHER) ridx = (i < NVOX) ? nidx[(size_t)(k + 1) * NVOX + i] : NVOX;
            else        ridx = i;
            bool ok = (ridx < NVOX);
            const char* src = (const char*)(xsrc + (size_t)(ok ? ridx : 0) * CIN);
            uint32_t dst = sA + (((buf ^ 1) * 2 + half)) * TB + r * RB;
            #pragma unroll
            for (int c = 0; c < CHUNKS; c++)
                cp16(dst + ((c ^ (r & SWZ)) << 4), src + c * 16, ok ? 16u : 0u);
            cp_commit();
            cp_wait<1>();   // A(k) + W(k) done; A(k+1) in flight
        } else {
            cp_wait<0>();
        }
        __syncthreads();

        // ---- compute ----
        const uint32_t aH = sA + (buf * 2 + 0) * TB;
        const uint32_t aL = sA + (buf * 2 + 1) * TB;
        #pragma unroll
        for (int ks = 0; ks < KSTEPS; ks++) {
            const int kc0 = ks * 2;
            uint32_t ah[2][4], al[2][4], bh[4][4], bl[4][4];
            #pragma unroll
            for (int mt = 0; mt < 2; mt++) {
                int row = wm * 32 + mt * 16 + (lane & 15);
                int c   = kc0 + (lane >> 4);
                uint32_t ad = row * RB + (((c ^ (row & SWZ))) << 4);
                ldsm4(ah[mt], aH + ad);
                ldsm4(al[mt], aL + ad);
            }
            #pragma unroll
            for (int np = 0; np < 4; np++) {
                int n = wn * 64 + np * 16 + (lane & 7) + ((lane & 16) ? 8 : 0);
                int c = kc0 + ((lane >> 3) & 1);
                uint32_t ad = n * RB + (((c ^ (n & SWZ))) << 4);
                ldsm4(bh[np], sW + ad);
                ldsm4(bl[np], sW + TB + ad);
            }
            #pragma unroll
            for (int mt = 0; mt < 2; mt++)
                #pragma unroll
                for (int np = 0; np < 4; np++)
                    #pragma unroll
                    for (int s = 0; s < 2; s++) {
                        float* C = acc[mt][np * 2 + s];
                        mma16816(C, ah[mt], &bh[np][s * 2]);
                        mma16816(C, ah[mt], &bl[np][s * 2]);
                        mma16816(C, al[mt], &bh[np][s * 2]);
                    }
        }
        buf ^= 1;
    }
    __syncthreads();

    // ---- epilogue ----
    if (EPI == 0) {
        #pragma unroll
        for (int mt = 0; mt < 2; mt++) {
            int row0 = base + wm * 32 + mt * 16 + g;
            #pragma unroll
            for (int nt = 0; nt < 8; nt++) {
                int col = wn * 64 + nt * 8 + tig * 2;
                float v0 = silu_f(acc[mt][nt][0] + bias_s[col]);
                float v1 = silu_f(acc[mt][nt][1] + bias_s[col + 1]);
                float v2 = silu_f(acc[mt][nt][2] + bias_s[col]);
                float v3 = silu_f(acc[mt][nt][3] + bias_s[col + 1]);
                __nv_bfloat16 h0 = __float2bfloat16_rn(v0), h1 = __float2bfloat16_rn(v1);
                __nv_bfloat16 h2 = __float2bfloat16_rn(v2), h3 = __float2bfloat16_rn(v3);
                uint32_t hw0 = (uint32_t)__bfloat16_as_ushort(h0) | ((uint32_t)__bfloat16_as_ushort(h1) << 16);
                uint32_t hw1 = (uint32_t)__bfloat16_as_ushort(h2) | ((uint32_t)__bfloat16_as_ushort(h3) << 16);
                uint32_t lw0 = (uint32_t)__bfloat16_as_ushort(__float2bfloat16_rn(v0 - __bfloat162float(h0)))
                             | ((uint32_t)__bfloat16_as_ushort(__float2bfloat16_rn(v1 - __bfloat162float(h1))) << 16);
                uint32_t lw1 = (uint32_t)__bfloat16_as_ushort(__float2bfloat16_rn(v2 - __bfloat162float(h2)))
                             | ((uint32_t)__bfloat16_as_ushort(__float2bfloat16_rn(v3 - __bfloat162float(h3))) << 16);
                if (row0 < NVOX) {
                    *(uint32_t*)(ohi + (size_t)row0 * CH + col) = hw0;
                    *(uint32_t*)(olo + (size_t)row0 * CH + col) = lw0;
                }
                if (row0 + 8 < NVOX) {
                    *(uint32_t*)(ohi + (size_t)(row0 + 8) * CH + col) = hw1;
                    *(uint32_t*)(olo + (size_t)(row0 + 8) * CH + col) = lw1;
                }
            }
        }
    } else {
        #pragma unroll
        for (int mt = 0; mt < 2; mt++) {
            float s0 = 0.f, s1 = 0.f;
            #pragma unroll
            for (int nt = 0; nt < 8; nt++) {
                int col = wn * 64 + nt * 8 + tig * 2;
                s0 += silu_f(acc[mt][nt][0] + bias_s[col])     * w4_s[col];
                s0 += silu_f(acc[mt][nt][1] + bias_s[col + 1]) * w4_s[col + 1];
                s1 += silu_f(acc[mt][nt][2] + bias_s[col])     * w4_s[col];
                s1 += silu_f(acc[mt][nt][3] + bias_s[col + 1]) * w4_s[col + 1];
            }
            // reduce over the 4 lanes of each quad (same row)
            s0 += __shfl_xor_sync(0xffffffffu, s0, 1);
            s0 += __shfl_xor_sync(0xffffffffu, s0, 2);
            s1 += __shfl_xor_sync(0xffffffffu, s1, 1);
            s1 += __shfl_xor_sync(0xffffffffu, s1, 2);
            if (tig == 0) {  // deterministic: unique (wn,row) writer
                red[wn * 128 + wm * 32 + mt * 16 + g]     = s0;
                red[wn * 128 + wm * 32 + mt * 16 + g + 8] = s1;
            }
        }
        __syncthreads();
        if (tid < 128) {
            int i = base + tid;
            if (i < NVOX) ofl[i] = red[tid] + red[128 + tid] + b4[0];
        }
    }
}

// ---------------------------------------------------------------------------
extern "C" void kernel_launch(void* const* d_in, const int* in_sizes, int n_in,
                              void* d_out, int out_size)
{
    const float* feat = (const float*)d_in[0];
    const int*   t    = (const int*)  d_in[1];
    const int*   nidx = (const int*)  d_in[2];
    const float* W1   = (const float*)d_in[3];
    const float* b1   = (const float*)d_in[4];
    const float* W2   = (const float*)d_in[5];
    const float* b2   = (const float*)d_in[6];
    const float* W3   = (const float*)d_in[7];
    const float* b3   = (const float*)d_in[8];
    const float* W4   = (const float*)d_in[9];
    const float* b4   = (const float*)d_in[10];
    float* out = (float*)d_out;

    __nv_bfloat16 *pxh, *pxl, *ph1h, *ph1l, *ph2h, *ph2l;
    __nv_bfloat16 *pw1h, *pw1l, *pw2h, *pw2l, *pw3h, *pw3l;
    cudaGetSymbolAddress((void**)&pxh,  g_x_hi);
    cudaGetSymbolAddress((void**)&pxl,  g_x_lo);
    cudaGetSymbolAddress((void**)&ph1h, g_h1_hi);
    cudaGetSymbolAddress((void**)&ph1l, g_h1_lo);
    cudaGetSymbolAddress((void**)&ph2h, g_h2_hi);
    cudaGetSymbolAddress((void**)&ph2l, g_h2_lo);
    cudaGetSymbolAddress((void**)&pw1h, g_w1_hi);
    cudaGetSymbolAddress((void**)&pw1l, g_w1_lo);
    cudaGetSymbolAddress((void**)&pw2h, g_w2_hi);
    cudaGetSymbolAddress((void**)&pw2l, g_w2_lo);
    cudaGetSymbolAddress((void**)&pw3h, g_w3_hi);
    cudaGetSymbolAddress((void**)&pw3l, g_w3_lo);

    // smem: 2048 header + W hi/lo + A double-buffered hi/lo (6 tiles)
    const int smem_l1 = 2048 + 6 * (128 * 16 * 2);    //  26,624 B
    const int smem_l2 = 2048 + 6 * (128 * 128 * 2);   // 198,656 B
    cudaFuncSetAttribute(conv_mma<16, 27, true, 0>,
                         cudaFuncAttributeMaxDynamicSharedMemorySize, smem_l1);
    cudaFuncSetAttribute(conv_mma<128, 27, true, 0>,
                         cudaFuncAttributeMaxDynamicSharedMemorySize, smem_l2);
    cudaFuncSetAttribute(conv_mma<128, 1, false, 1>,
                         cudaFuncAttributeMaxDynamicSharedMemorySize, smem_l2);

    embed_k<<<(NVOX + 255) / 256, 256>>>(feat, t, pxh, pxl);
    prep_w1_k<<<(27 * 128 * 16  + 255) / 256, 256>>>(W1, pw1h, pw1l);
    prep_w2_k<<<(27 * 128 * 128 + 255) / 256, 256>>>(W2, pw2h, pw2l);
    prep_w3_k<<<(128 * 128      + 255) / 256, 256>>>(W3, pw3h, pw3l);

    conv_mma<16, 27, true, 0><<<NT, NTHREADS, smem_l1>>>(
        pxh, pxl, nidx, pw1h, pw1l, b1, nullptr, nullptr, ph1h, ph1l, nullptr);
    conv_mma<128, 27, true, 0><<<NT, NTHREADS, smem_l2>>>(
        ph1h, ph1l, nidx, pw2h, pw2l, b2, nullptr, nullptr, ph2h, ph2l, nullptr);
    conv_mma<128, 1, false, 1><<<NT, NTHREADS, smem_l2>>>(
        ph2h, ph2l, nullptr, pw3h, pw3l, b3, W4, b4, nullptr, nullptr, out);
}

// round 4
// speedup vs baseline: 1.8499x; 1.2620x over previous
#include <cuda_runtime.h>
#include <cuda_fp16.h>
#include <math.h>
#include <stdint.h>

#define NVOX 200000
#define CH   128
#define MT   128                           // voxels per CTA tile
#define NT   ((NVOX + MT - 1) / MT)        // 1563 CTAs
#define NTHREADS 256
#define LOSCALE 2048.0f                    // 2^11 pre-scale for W-lo term

// ---------------------------------------------------------------------------
// Device scratch
// ---------------------------------------------------------------------------
__device__ __half g_x [(size_t)NVOX * 16];
__device__ __half g_h1[(size_t)NVOX * CH];
__device__ __half g_h2[(size_t)NVOX * CH];
__device__ __half g_w1_hi[27 * 128 * 16];   // [k][cout][j pad16]
__device__ __half g_w1_lo[27 * 128 * 16];
__device__ __half g_w2_hi[27 * 128 * 128];  // [k][cout][j]
__device__ __half g_w2_lo[27 * 128 * 128];
__device__ __half g_w3_hi[128 * 128];       // [cout][j]
__device__ __half g_w3_lo[128 * 128];

// ---------------------------------------------------------------------------
// Portable PTX helpers (legal at compute_103)
// ---------------------------------------------------------------------------
__device__ __forceinline__ uint32_t smem_u32(const void* p) {
    uint32_t a;
    asm("{ .reg .u64 t; cvta.to.shared.u64 t, %1; cvt.u32.u64 %0, t; }" : "=r"(a) : "l"(p));
    return a;
}
__device__ __forceinline__ void cp16(uint32_t dst, const void* src, uint32_t sz) {
    asm volatile("cp.async.cg.shared.global [%0], [%1], 16, %2;"
                 :: "r"(dst), "l"(src), "r"(sz) : "memory");
}
__device__ __forceinline__ void cp_commit() {
    asm volatile("cp.async.commit_group;" ::: "memory");
}
template<int N> __device__ __forceinline__ void cp_wait() {
    asm volatile("cp.async.wait_group %0;" :: "n"(N) : "memory");
}
__device__ __forceinline__ void ldsm4(uint32_t* r, uint32_t a) {
    asm volatile("ldmatrix.sync.aligned.m8n8.x4.shared.b16 {%0,%1,%2,%3}, [%4];"
                 : "=r"(r[0]), "=r"(r[1]), "=r"(r[2]), "=r"(r[3]) : "r"(a));
}
__device__ __forceinline__ void mma16816(float* c, const uint32_t* a, const uint32_t* b) {
    asm volatile(
        "mma.sync.aligned.m16n8k16.row.col.f32.f16.f16.f32 "
        "{%0,%1,%2,%3}, {%4,%5,%6,%7}, {%8,%9}, {%0,%1,%2,%3};"
        : "+f"(c[0]), "+f"(c[1]), "+f"(c[2]), "+f"(c[3])
        : "r"(a[0]), "r"(a[1]), "r"(a[2]), "r"(a[3]), "r"(b[0]), "r"(b[1]));
}
__device__ __forceinline__ float silu_f(float v) { return v / (1.f + __expf(-v)); }

// ---------------------------------------------------------------------------
// Embedding -> single fp16, 16-wide padded rows
// ---------------------------------------------------------------------------
__global__ void embed_k(const float* __restrict__ feat, const int* __restrict__ t,
                        __half* __restrict__ x)
{
    int i = blockIdx.x * blockDim.x + threadIdx.x;
    if (i >= NVOX) return;
    const float PI_F = 3.14159265358979323846f;
    float tv = (float)t[i];
    float vals[7];
    vals[0] = feat[i];
    vals[1] = sinf(tv * PI_F);
    vals[2] = sinf(tv * (2.f * PI_F));
    vals[3] = sinf(tv * (4.f * PI_F));
    vals[4] = cosf(tv * PI_F);
    vals[5] = cosf(tv * (2.f * PI_F));
    vals[6] = cosf(tv * (4.f * PI_F));
    #pragma unroll
    for (int j = 0; j < 16; j++)
        x[(size_t)i * 16 + j] = __float2half_rn((j < 7) ? vals[j] : 0.f);
}

// Weight prep: transpose to [.., cout, j]; split w = wh + wl/2048 (wl pre-scaled)
__global__ void prep_w1_k(const float* __restrict__ W1,
                          __half* __restrict__ wh, __half* __restrict__ wl)
{
    int idx = blockIdx.x * blockDim.x + threadIdx.x;
    if (idx >= 27 * 128 * 16) return;
    int j = idx & 15, c = (idx >> 4) & 127, k = idx >> 11;
    float v = (j < 7) ? W1[((size_t)k * 7 + j) * 128 + c] : 0.f;
    __half h = __float2half_rn(v);
    wh[idx] = h;
    wl[idx] = __float2half_rn((v - __half2float(h)) * LOSCALE);
}
__global__ void prep_w2_k(const float* __restrict__ W2,
                          __half* __restrict__ wh, __half* __restrict__ wl)
{
    int idx = blockIdx.x * blockDim.x + threadIdx.x;
    if (idx >= 27 * 128 * 128) return;
    int j = idx & 127, c = (idx >> 7) & 127, k = idx >> 14;
    float v = W2[((size_t)k * 128 + j) * 128 + c];
    __half h = __float2half_rn(v);
    wh[idx] = h;
    wl[idx] = __float2half_rn((v - __half2float(h)) * LOSCALE);
}
__global__ void prep_w3_k(const float* __restrict__ W3,
                          __half* __restrict__ wh, __half* __restrict__ wl)
{
    int idx = blockIdx.x * blockDim.x + threadIdx.x;
    if (idx >= 128 * 128) return;
    int j = idx & 127, c = idx >> 7;
    float v = W3[(size_t)j * 128 + c];
    __half h = __float2half_rn(v);
    wh[idx] = h;
    wl[idx] = __float2half_rn((v - __half2float(h)) * LOSCALE);
}

// ---------------------------------------------------------------------------
// Gathered conv: fp16 mma.sync, W split hi/lo (2 MMAs per chunk), fp32 accum.
// A = activations, single fp16. Dual accumulator sets, folded in epilogue.
//  EPI 0: silu -> fp16 store.  EPI 1: fused silu -> dot(W4) + b4 -> float out.
// Tile: 128 voxels x 128 couts, 8 warps (4x2), warp tile 32x64.
// ---------------------------------------------------------------------------
template<int CIN, int NK, bool GATHER, int EPI>
__global__ void __launch_bounds__(NTHREADS)
conv_mma(const __half* __restrict__ xin,
         const int* __restrict__ nidx,
         const __half* __restrict__ whi, const __half* __restrict__ wlo,
         const float* __restrict__ bias,
         const float* __restrict__ w4, const float* __restrict__ b4,
         __half* __restrict__ oh, float* __restrict__ ofl)
{
    constexpr int CHUNKS = CIN / 8;           // 16B chunks per row
    constexpr int CH2    = CHUNKS / 2;
    constexpr int SWZ    = (CHUNKS >= 8) ? 7 : (CHUNKS - 1);
    constexpr int RB     = CHUNKS * 16;       // row bytes
    constexpr int TB     = 128 * RB;          // tile bytes
    constexpr int KSTEPS = CIN / 16;
    constexpr uint32_t HDR = 2048;

    extern __shared__ char smem[];
    const uint32_t sb = smem_u32(smem);
    float* bias_s = (float*)smem;             // [128]
    float* w4_s   = (float*)(smem + 512);     // [128]
    float* red    = (float*)(smem + 1024);    // [2][128]

    const int tid  = threadIdx.x;
    const int wid  = tid >> 5, lane = tid & 31;
    const int wm   = wid >> 1, wn = wid & 1;  // warp grid 4x2
    const int g    = lane >> 2, tig = lane & 3;
    const int base = blockIdx.x * MT;

    const uint32_t sW = sb + HDR;             // W hi tile (lo at +TB)
    const uint32_t sA = sb + HDR + 2 * TB;    // A[buf]

    if (tid < 128) {
        bias_s[tid] = bias[tid];
        if (EPI == 1) { w4_s[tid] = w4[tid]; red[tid] = 0.f; red[128 + tid] = 0.f; }
    }

    const int half = tid & 1, r = tid >> 1;   // staging map: 2 threads/row

    // ---- prologue: issue A(0) ----
    {
        int i = base + r;
        int ridx;
        if (GATHER) ridx = (i < NVOX) ? nidx[(size_t)0 * NVOX + i] : NVOX;
        else        ridx = i;
        bool ok = (ridx < NVOX);
        const char* src = (const char*)(xin + (size_t)(ok ? ridx : 0) * CIN) + half * (CH2 * 16);
        uint32_t dst = sA + r * RB;
        #pragma unroll
        for (int c = 0; c < CH2; c++) {
            int cc = half * CH2 + c;
            cp16(dst + ((cc ^ (r & SWZ)) << 4), src + c * 16, ok ? 16u : 0u);
        }
    }
    cp_commit();

    float acc[2][2][8][4];   // [term hi/lo][mt][nt][q]
    #pragma unroll
    for (int tm = 0; tm < 2; tm++)
        #pragma unroll
        for (int a = 0; a < 2; a++)
            #pragma unroll
            for (int b = 0; b < 8; b++)
                #pragma unroll
                for (int q = 0; q < 4; q++) acc[tm][a][b][q] = 0.f;

    int buf = 0;
    for (int k = 0; k < NK; k++) {
        __syncthreads();   // W buffer free (prev compute done)

        // ---- issue W(k): half selects hi/lo array, full row per thread ----
        {
            const __half* wsrc = half ? wlo : whi;
            const char* src = (const char*)(wsrc + ((size_t)k * 128 + r) * CIN);
            uint32_t dst = sW + half * TB + r * RB;
            #pragma unroll
            for (int c = 0; c < CHUNKS; c++)
                cp16(dst + ((c ^ (r & SWZ)) << 4), src + c * 16, 16u);
        }
        cp_commit();

        // ---- issue A(k+1) ----
        if (k + 1 < NK) {
            int i = base + r;
            int ridx;
            if (GATHER) ridx = (i < NVOX) ? nidx[(size_t)(k + 1) * NVOX + i] : NVOX;
            else        ridx = i;
            bool ok = (ridx < NVOX);
            const char* src = (const char*)(xin + (size_t)(ok ? ridx : 0) * CIN) + half * (CH2 * 16);
            uint32_t dst = sA + (buf ^ 1) * TB + r * RB;
            #pragma unroll
            for (int c = 0; c < CH2; c++) {
                int cc = half * CH2 + c;
                cp16(dst + ((cc ^ (r & SWZ)) << 4), src + c * 16, ok ? 16u : 0u);
            }
            cp_commit();
            cp_wait<1>();   // A(k) + W(k) done; A(k+1) in flight
        } else {
            cp_wait<0>();
        }
        __syncthreads();

        // ---- compute ----
        const uint32_t aT = sA + buf * TB;
        #pragma unroll
        for (int ks = 0; ks < KSTEPS; ks++) {
            const int kc0 = ks * 2;
            uint32_t am[2][4], bh[4][4], bl[4][4];
            #pragma unroll
            for (int mt = 0; mt < 2; mt++) {
                int row = wm * 32 + mt * 16 + (lane & 15);
                int c   = kc0 + (lane >> 4);
                ldsm4(am[mt], aT + row * RB + (((c ^ (row & SWZ))) << 4));
            }
            #pragma unroll
            for (int np = 0; np < 4; np++) {
                int n = wn * 64 + np * 16 + (lane & 7) + ((lane & 16) ? 8 : 0);
                int c = kc0 + ((lane >> 3) & 1);
                uint32_t ad = n * RB + (((c ^ (n & SWZ))) << 4);
                ldsm4(bh[np], sW + ad);
                ldsm4(bl[np], sW + TB + ad);
            }
            #pragma unroll
            for (int mt = 0; mt < 2; mt++)
                #pragma unroll
                for (int np = 0; np < 4; np++)
                    #pragma unroll
                    for (int s = 0; s < 2; s++) {
                        mma16816(acc[0][mt][np * 2 + s], am[mt], &bh[np][s * 2]);
                        mma16816(acc[1][mt][np * 2 + s], am[mt], &bl[np][s * 2]);
                    }
        }
        buf ^= 1;
    }
    __syncthreads();

    // ---- epilogue: fold lo term, bias, silu ----
    const float INV = 1.0f / LOSCALE;
    if (EPI == 0) {
        #pragma unroll
        for (int mt = 0; mt < 2; mt++) {
            int row0 = base + wm * 32 + mt * 16 + g;
            #pragma unroll
            for (int nt = 0; nt < 8; nt++) {
                int col = wn * 64 + nt * 8 + tig * 2;
                float v0 = silu_f(fmaf(acc[1][mt][nt][0], INV, acc[0][mt][nt][0]) + bias_s[col]);
                float v1 = silu_f(fmaf(acc[1][mt][nt][1], INV, acc[0][mt][nt][1]) + bias_s[col + 1]);
                float v2 = silu_f(fmaf(acc[1][mt][nt][2], INV, acc[0][mt][nt][2]) + bias_s[col]);
                float v3 = silu_f(fmaf(acc[1][mt][nt][3], INV, acc[0][mt][nt][3]) + bias_s[col + 1]);
                __half2 p0 = __floats2half2_rn(v0, v1);
                __half2 p1 = __floats2half2_rn(v2, v3);
                if (row0 < NVOX)
                    *(__half2*)(oh + (size_t)row0 * CH + col) = p0;
                if (row0 + 8 < NVOX)
                    *(__half2*)(oh + (size_t)(row0 + 8) * CH + col) = p1;
            }
        }
    } else {
        #pragma unroll
        for (int mt = 0; mt < 2; mt++) {
            float s0 = 0.f, s1 = 0.f;
            #pragma unroll
            for (int nt = 0; nt < 8; nt++) {
                int col = wn * 64 + nt * 8 + tig * 2;
                s0 += silu_f(fmaf(acc[1][mt][nt][0], INV, acc[0][mt][nt][0]) + bias_s[col])     * w4_s[col];
                s0 += silu_f(fmaf(acc[1][mt][nt][1], INV, acc[0][mt][nt][1]) + bias_s[col + 1]) * w4_s[col + 1];
                s1 += silu_f(fmaf(acc[1][mt][nt][2], INV, acc[0][mt][nt][2]) + bias_s[col])     * w4_s[col];
                s1 += silu_f(fmaf(acc[1][mt][nt][3], INV, acc[0][mt][nt][3]) + bias_s[col + 1]) * w4_s[col + 1];
            }
            s0 += __shfl_xor_sync(0xffffffffu, s0, 1);
            s0 += __shfl_xor_sync(0xffffffffu, s0, 2);
            s1 += __shfl_xor_sync(0xffffffffu, s1, 1);
            s1 += __shfl_xor_sync(0xffffffffu, s1, 2);
            if (tig == 0) {
                red[wn * 128 + wm * 32 + mt * 16 + g]     = s0;
                red[wn * 128 + wm * 32 + mt * 16 + g + 8] = s1;
            }
        }
        __syncthreads();
        if (tid < 128) {
            int i = base + tid;
            if (i < NVOX) ofl[i] = red[tid] + red[128 + tid] + b4[0];
        }
    }
}

// ---------------------------------------------------------------------------
extern "C" void kernel_launch(void* const* d_in, const int* in_sizes, int n_in,
                              void* d_out, int out_size)
{
    const float* feat = (const float*)d_in[0];
    const int*   t    = (const int*)  d_in[1];
    const int*   nidx = (const int*)  d_in[2];
    const float* W1   = (const float*)d_in[3];
    const float* b1   = (const float*)d_in[4];
    const float* W2   = (const float*)d_in[5];
    const float* b2   = (const float*)d_in[6];
    const float* W3   = (const float*)d_in[7];
    const float* b3   = (const float*)d_in[8];
    const float* W4   = (const float*)d_in[9];
    const float* b4   = (const float*)d_in[10];
    float* out = (float*)d_out;

    __half *px, *ph1, *ph2, *pw1h, *pw1l, *pw2h, *pw2l, *pw3h, *pw3l;
    cudaGetSymbolAddress((void**)&px,   g_x);
    cudaGetSymbolAddress((void**)&ph1,  g_h1);
    cudaGetSymbolAddress((void**)&ph2,  g_h2);
    cudaGetSymbolAddress((void**)&pw1h, g_w1_hi);
    cudaGetSymbolAddress((void**)&pw1l, g_w1_lo);
    cudaGetSymbolAddress((void**)&pw2h, g_w2_hi);
    cudaGetSymbolAddress((void**)&pw2l, g_w2_lo);
    cudaGetSymbolAddress((void**)&pw3h, g_w3_hi);
    cudaGetSymbolAddress((void**)&pw3l, g_w3_lo);

    // smem: 2048 header + W hi/lo + A double-buffered (4 tiles)
    const int smem_l1 = 2048 + 4 * (128 * 16 * 2);    //  18,432 B
    const int smem_l2 = 2048 + 4 * (128 * 128 * 2);   // 133,120 B
    cudaFuncSetAttribute(conv_mma<16, 27, true, 0>,
                         cudaFuncAttributeMaxDynamicSharedMemorySize, smem_l1);
    cudaFuncSetAttribute(conv_mma<128, 27, true, 0>,
                         cudaFuncAttributeMaxDynamicSharedMemorySize, smem_l2);
    cudaFuncSetAttribute(conv_mma<128, 1, false, 1>,
                         cudaFuncAttributeMaxDynamicSharedMemorySize, smem_l2);

    embed_k<<<(NVOX + 255) / 256, 256>>>(feat, t, px);
    prep_w1_k<<<(27 * 128 * 16  + 255) / 256, 256>>>(W1, pw1h, pw1l);
    prep_w2_k<<<(27 * 128 * 128 + 255) / 256, 256>>>(W2, pw2h, pw2l);
    prep_w3_k<<<(128 * 128      + 255) / 256, 256>>>(W3, pw3h, pw3l);

    conv_mma<16, 27, true, 0><<<NT, NTHREADS, smem_l1>>>(
        px, nidx, pw1h, pw1l, b1, nullptr, nullptr, ph1, nullptr);
    conv_mma<128, 27, true, 0><<<NT, NTHREADS, smem_l2>>>(
        ph1, nidx, pw2h, pw2l, b2, nullptr, nullptr, ph2, nullptr);
    conv_mma<128, 1, false, 1><<<NT, NTHREADS, smem_l2>>>(
        ph2, nullptr, pw3h, pw3l, b3, W4, b4, nullptr, out);
}

// round 16
// speedup vs baseline: 3.5940x; 1.9428x over previous
#include <cuda_runtime.h>
#include <cuda_fp16.h>
#include <math.h>
#include <stdint.h>

#define NVOX 200000
#define CH   128
#define MT   128
#define NT   ((NVOX + MT - 1) / MT)        // 1563
#define NTHREADS 256
#define LOSCALE 2048.0f
#define ACCSTRIDE 132

// ---------------------------------------------------------------------------
// Device scratch
// ---------------------------------------------------------------------------
__device__ __half g_x [(size_t)NVOX * 16];
__device__ __half g_h1[(size_t)NVOX * CH];
__device__ __half g_h2[(size_t)NVOX * CH];
__device__ __half g_w1_hi[27 * 128 * 16];
__device__ __half g_w1_lo[27 * 128 * 16];
__device__ __half g_w2_hi[27 * 128 * 128];
__device__ __half g_w2_lo[27 * 128 * 128];
__device__ __half g_w3_hi[128 * 128];
__device__ __half g_w3_lo[128 * 128];

// ---------------------------------------------------------------------------
// Portable PTX helpers
// ---------------------------------------------------------------------------
__device__ __forceinline__ uint32_t smem_u32(const void* p) {
    uint32_t a;
    asm("{ .reg .u64 t; cvta.to.shared.u64 t, %1; cvt.u32.u64 %0, t; }" : "=r"(a) : "l"(p));
    return a;
}
__device__ __forceinline__ void cp16(uint32_t dst, const void* src, uint32_t sz) {
    asm volatile("cp.async.cg.shared.global [%0], [%1], 16, %2;"
                 :: "r"(dst), "l"(src), "r"(sz) : "memory");
}
__device__ __forceinline__ void cp_commit() {
    asm volatile("cp.async.commit_group;" ::: "memory");
}
template<int N> __device__ __forceinline__ void cp_wait() {
    asm volatile("cp.async.wait_group %0;" :: "n"(N) : "memory");
}
__device__ __forceinline__ void ldsm4(uint32_t* r, uint32_t a) {
    asm volatile("ldmatrix.sync.aligned.m8n8.x4.shared.b16 {%0,%1,%2,%3}, [%4];"
                 : "=r"(r[0]), "=r"(r[1]), "=r"(r[2]), "=r"(r[3]) : "r"(a));
}
__device__ __forceinline__ void mma16816(float* c, const uint32_t* a, const uint32_t* b) {
    asm volatile(
        "mma.sync.aligned.m16n8k16.row.col.f32.f16.f16.f32 "
        "{%0,%1,%2,%3}, {%4,%5,%6,%7}, {%8,%9}, {%0,%1,%2,%3};"
        : "+f"(c[0]), "+f"(c[1]), "+f"(c[2]), "+f"(c[3])
        : "r"(a[0]), "r"(a[1]), "r"(a[2]), "r"(a[3]), "r"(b[0]), "r"(b[1]));
}
__device__ __forceinline__ float silu_f(float v) { return v / (1.f + __expf(-v)); }

// ---------------------------------------------------------------------------
// Embedding / weight prep
// ---------------------------------------------------------------------------
__global__ void embed_k(const float* __restrict__ feat, const int* __restrict__ t,
                        __half* __restrict__ x)
{
    int i = blockIdx.x * blockDim.x + threadIdx.x;
    if (i >= NVOX) return;
    const float PI_F = 3.14159265358979323846f;
    float tv = (float)t[i];
    float vals[7];
    vals[0] = feat[i];
    vals[1] = sinf(tv * PI_F);
    vals[2] = sinf(tv * (2.f * PI_F));
    vals[3] = sinf(tv * (4.f * PI_F));
    vals[4] = cosf(tv * PI_F);
    vals[5] = cosf(tv * (2.f * PI_F));
    vals[6] = cosf(tv * (4.f * PI_F));
    #pragma unroll
    for (int j = 0; j < 16; j++)
        x[(size_t)i * 16 + j] = __float2half_rn((j < 7) ? vals[j] : 0.f);
}
__global__ void prep_w1_k(const float* __restrict__ W1,
                          __half* __restrict__ wh, __half* __restrict__ wl)
{
    int idx = blockIdx.x * blockDim.x + threadIdx.x;
    if (idx >= 27 * 128 * 16) return;
    int j = idx & 15, c = (idx >> 4) & 127, k = idx >> 11;
    float v = (j < 7) ? W1[((size_t)k * 7 + j) * 128 + c] : 0.f;
    __half h = __float2half_rn(v);
    wh[idx] = h;
    wl[idx] = __float2half_rn((v - __half2float(h)) * LOSCALE);
}
__global__ void prep_w2_k(const float* __restrict__ W2,
                          __half* __restrict__ wh, __half* __restrict__ wl)
{
    int idx = blockIdx.x * blockDim.x + threadIdx.x;
    if (idx >= 27 * 128 * 128) return;
    int j = idx & 127, c = (idx >> 7) & 127, k = idx >> 14;
    float v = W2[((size_t)k * 128 + j) * 128 + c];
    __half h = __float2half_rn(v);
    wh[idx] = h;
    wl[idx] = __float2half_rn((v - __half2float(h)) * LOSCALE);
}
__global__ void prep_w3_k(const float* __restrict__ W3,
                          __half* __restrict__ wh, __half* __restrict__ wl)
{
    int idx = blockIdx.x * blockDim.x + threadIdx.x;
    if (idx >= 128 * 128) return;
    int j = idx & 127, c = idx >> 7;
    float v = W3[(size_t)j * 128 + c];
    __half h = __float2half_rn(v);
    wh[idx] = h;
    wl[idx] = __float2half_rn((v - __half2float(h)) * LOSCALE);
}

// ---------------------------------------------------------------------------
// Compacted sparse conv (layers 1 & 2): per (tile,k) ballot-scan the valid
// rows, gather only those, GEMM at M=16 granularity, scatter-add into an
// fp32 smem accumulator. Warp w owns cols [16w,16w+16) -> race-free.
// ---------------------------------------------------------------------------
template<int CIN, int NK>
__global__ void __launch_bounds__(NTHREADS)
conv_sparse(const __half* __restrict__ xin,
            const int* __restrict__ nidx,
            const __half* __restrict__ whi, const __half* __restrict__ wlo,
            const float* __restrict__ bias,
            __half* __restrict__ oh)
{
    constexpr int CHUNKS = CIN / 8;
    constexpr int SWZ    = (CHUNKS >= 8) ? 7 : (CHUNKS - 1);
    constexpr int RB     = CHUNKS * 16;
    constexpr int TBW    = 128 * RB;
    constexpr int TBA    = 128 * RB;
    constexpr int KSTEPS = CIN / 16;
    constexpr uint32_t HDR   = 4096;
    constexpr uint32_t OFF_ACC = HDR;
    constexpr uint32_t ACCB  = 128 * ACCSTRIDE * 4;     // 67584
    constexpr uint32_t OFF_W = OFF_ACC + ACCB;
    constexpr uint32_t OFF_A = OFF_W + 2 * TBW;

    extern __shared__ char smem[];
    const uint32_t sb = smem_u32(smem);
    float* bias_s = (float*)smem;                        // [128]
    int*   jidx   = (int*)(smem + 512);                  // [2][128]
    unsigned char* pos = (unsigned char*)(smem + 512 + 1024);  // [2][128]
    int*   wsum   = (int*)(smem + 512 + 1024 + 256);     // [2][4]
    float* accp   = (float*)(smem + OFF_ACC);

    const int tid  = threadIdx.x;
    const int w    = tid >> 5, lane = tid & 31;
    const int g    = lane >> 2, tig = lane & 3;
    const int base = blockIdx.x * MT;

    if (tid < 128) bias_s[tid] = bias[tid];

    // ---- compaction phase 1 for k=0 ----
    int c_j = NVOX; bool c_valid = false; int c_pre = 0;
    {
        if (tid < 128) {
            int i = base + tid;
            c_j = (i < NVOX) ? nidx[(size_t)0 * NVOX + i] : NVOX;
            c_valid = (c_j < NVOX);
            unsigned mask = __ballot_sync(0xffffffffu, c_valid);
            c_pre = __popc(mask & ((1u << lane) - 1));
            if (lane == 0) wsum[0 * 4 + w] = __popc(mask);
        } else {
            __ballot_sync(0xffffffffu, false);  // warps 4-7: harmless
        }
    }
    __syncthreads();
    if (tid < 128 && c_valid) {
        int wb = 0;
        #pragma unroll
        for (int q = 0; q < 4; q++) if (q < w) wb += wsum[0 * 4 + q];
        int slot = wb + c_pre;
        pos[0 * 128 + slot] = (unsigned char)tid;
        jidx[0 * 128 + slot] = c_j;
    }
    __syncthreads();

    // ---- issue A(0) ----
    {
        int cnt0 = wsum[0] + wsum[1] + wsum[2] + wsum[3];
        for (int idx = tid; idx < cnt0 * CHUNKS; idx += NTHREADS) {
            int p = idx / CHUNKS, c = idx % CHUNKS;
            const char* src = (const char*)(xin + (size_t)jidx[p] * CIN) + c * 16;
            cp16(sb + OFF_A + p * RB + ((c ^ (p & SWZ)) << 4), src, 16u);
        }
    }
    cp_commit();
    // ---- issue W(0) ----
    {
        #pragma unroll
        for (int it = 0; it < CHUNKS; it++) {
            int idx = it * NTHREADS + tid;
            int half = idx / (128 * CHUNKS);
            int rem  = idx % (128 * CHUNKS);
            int r = rem / CHUNKS, c = rem % CHUNKS;
            const __half* ws = half ? wlo : whi;
            const char* src = (const char*)(ws + ((size_t)0 * 128 + r) * CIN) + c * 16;
            cp16(sb + OFF_W + half * TBW + r * RB + ((c ^ (r & SWZ)) << 4), src, 16u);
        }
    }
    cp_commit();

    // ---- zero accumulator ----
    for (int idx = tid; idx < 128 * ACCSTRIDE; idx += NTHREADS) accp[idx] = 0.f;

    const float INV = 1.0f / LOSCALE;
    int cb = 0, ab = 0;

    for (int k = 0; k < NK; k++) {
        if (k + 1 < NK) {
            const int nb = cb ^ 1;
            // compaction phase 1 (k+1)
            if (tid < 128) {
                int i = base + tid;
                c_j = (i < NVOX) ? nidx[(size_t)(k + 1) * NVOX + i] : NVOX;
                c_valid = (c_j < NVOX);
                unsigned mask = __ballot_sync(0xffffffffu, c_valid);
                c_pre = __popc(mask & ((1u << lane) - 1));
                if (lane == 0) wsum[nb * 4 + w] = __popc(mask);
            } else {
                __ballot_sync(0xffffffffu, false);
            }
            __syncthreads();
            // phase 2
            if (tid < 128 && c_valid) {
                int wb = 0;
                #pragma unroll
                for (int q = 0; q < 4; q++) if (q < w) wb += wsum[nb * 4 + q];
                int slot = wb + c_pre;
                pos[nb * 128 + slot] = (unsigned char)tid;
                jidx[nb * 128 + slot] = c_j;
            }
            __syncthreads();
            // issue A(k+1)
            {
                int cntn = wsum[nb * 4] + wsum[nb * 4 + 1] + wsum[nb * 4 + 2] + wsum[nb * 4 + 3];
                int nab = ab ^ 1;
                for (int idx = tid; idx < cntn * CHUNKS; idx += NTHREADS) {
                    int p = idx / CHUNKS, c = idx % CHUNKS;
                    const char* src = (const char*)(xin + (size_t)jidx[nb * 128 + p] * CIN) + c * 16;
                    cp16(sb + OFF_A + nab * TBA + p * RB + ((c ^ (p & SWZ)) << 4), src, 16u);
                }
            }
            cp_commit();
            cp_wait<1>();    // drain A(k), W(k); keep A(k+1) in flight
        } else {
            cp_wait<0>();
        }
        __syncthreads();

        // ---- compute + scatter for k ----
        {
            const int cnt = wsum[cb * 4] + wsum[cb * 4 + 1] + wsum[cb * 4 + 2] + wsum[cb * 4 + 3];
            const int nmt = (cnt + 15) >> 4;
            const uint32_t aT = sb + OFF_A + ab * TBA;
            const uint32_t bH = sb + OFF_W;
            const uint32_t bL = sb + OFF_W + TBW;
            const int nrow = w * 16 + (lane & 7) + ((lane & 16) ? 8 : 0);
            const int cBo  = (lane >> 3) & 1;
            const int rA   = lane & 15, cAo = lane >> 4;

            for (int mt = 0; mt < nmt; mt++) {
                float chv[2][4], clv[2][4];
                #pragma unroll
                for (int s = 0; s < 2; s++)
                    #pragma unroll
                    for (int q = 0; q < 4; q++) { chv[s][q] = 0.f; clv[s][q] = 0.f; }
                const int arow = mt * 16 + rA;
                #pragma unroll
                for (int ks = 0; ks < KSTEPS; ks++) {
                    uint32_t am[4], bh[4], bl[4];
                    int ca = ks * 2 + cAo;
                    ldsm4(am, aT + arow * RB + (((ca ^ (arow & SWZ))) << 4));
                    int cbb = ks * 2 + cBo;
                    uint32_t bad = nrow * RB + (((cbb ^ (nrow & SWZ))) << 4);
                    ldsm4(bh, bH + bad);
                    ldsm4(bl, bL + bad);
                    mma16816(chv[0], am, &bh[0]); mma16816(chv[1], am, &bh[2]);
                    mma16816(clv[0], am, &bl[0]); mma16816(clv[1], am, &bl[2]);
                }
                const int p0 = mt * 16 + g, p1 = p0 + 8;
                #pragma unroll
                for (int s = 0; s < 2; s++) {
                    const int col = w * 16 + s * 8 + tig * 2;
                    if (p0 < cnt) {
                        int row = pos[cb * 128 + p0];
                        float* a0 = accp + row * ACCSTRIDE + col;
                        a0[0] += fmaf(clv[s][0], INV, chv[s][0]);
                        a0[1] += fmaf(clv[s][1], INV, chv[s][1]);
                    }
                    if (p1 < cnt) {
                        int row = pos[cb * 128 + p1];
                        float* a1 = accp + row * ACCSTRIDE + col;
                        a1[0] += fmaf(clv[s][2], INV, chv[s][2]);
                        a1[1] += fmaf(clv[s][3], INV, chv[s][3]);
                    }
                }
            }
        }
        __syncthreads();

        // ---- issue W(k+1) (single-buffered; all compute done) ----
        if (k + 1 < NK) {
            #pragma unroll
            for (int it = 0; it < CHUNKS; it++) {
                int idx = it * NTHREADS + tid;
                int half = idx / (128 * CHUNKS);
                int rem  = idx % (128 * CHUNKS);
                int r = rem / CHUNKS, c = rem % CHUNKS;
                const __half* ws = half ? wlo : whi;
                const char* src = (const char*)(ws + ((size_t)(k + 1) * 128 + r) * CIN) + c * 16;
                cp16(sb + OFF_W + half * TBW + r * RB + ((c ^ (r & SWZ)) << 4), src, 16u);
            }
            cp_commit();
            cb ^= 1; ab ^= 1;
        }
    }

    // ---- epilogue: bias + silu -> fp16 ----
    __syncthreads();
    {
        const int row = tid >> 1, ch0 = (tid & 1) * 64;
        const int i = base + row;
        if (i < NVOX) {
            const float* ar = accp + row * ACCSTRIDE + ch0;
            #pragma unroll
            for (int c0 = 0; c0 < 64; c0 += 8) {
                float4 v0 = *(const float4*)(ar + c0);
                float4 v1 = *(const float4*)(ar + c0 + 4);
                const float* bp = bias_s + ch0 + c0;
                __half2 h0 = __floats2half2_rn(silu_f(v0.x + bp[0]), silu_f(v0.y + bp[1]));
                __half2 h1 = __floats2half2_rn(silu_f(v0.z + bp[2]), silu_f(v0.w + bp[3]));
                __half2 h2 = __floats2half2_rn(silu_f(v1.x + bp[4]), silu_f(v1.y + bp[5]));
                __half2 h3 = __floats2half2_rn(silu_f(v1.z + bp[6]), silu_f(v1.w + bp[7]));
                uint4 pk;
                pk.x = *(uint32_t*)&h0; pk.y = *(uint32_t*)&h1;
                pk.z = *(uint32_t*)&h2; pk.w = *(uint32_t*)&h3;
                *(uint4*)(oh + (size_t)i * CH + ch0 + c0) = pk;
            }
        }
    }
}

// ---------------------------------------------------------------------------
// Dense conv (layer 3 + fused output), from R4.
// ---------------------------------------------------------------------------
template<int CIN, int NK, bool GATHER, int EPI>
__global__ void __launch_bounds__(NTHREADS)
conv_mma(const __half* __restrict__ xin,
         const int* __restrict__ nidx,
         const __half* __restrict__ whi, const __half* __restrict__ wlo,
         const float* __restrict__ bias,
         const float* __restrict__ w4, const float* __restrict__ b4,
         __half* __restrict__ oh, float* __restrict__ ofl)
{
    constexpr int CHUNKS = CIN / 8;
    constexpr int CH2    = CHUNKS / 2;
    constexpr int SWZ    = (CHUNKS >= 8) ? 7 : (CHUNKS - 1);
    constexpr int RB     = CHUNKS * 16;
    constexpr int TB     = 128 * RB;
    constexpr int KSTEPS = CIN / 16;
    constexpr uint32_t HDR = 2048;

    extern __shared__ char smem[];
    const uint32_t sb = smem_u32(smem);
    float* bias_s = (float*)smem;
    float* w4_s   = (float*)(smem + 512);
    float* red    = (float*)(smem + 1024);

    const int tid  = threadIdx.x;
    const int wid  = tid >> 5, lane = tid & 31;
    const int wm   = wid >> 1, wn = wid & 1;
    const int g    = lane >> 2, tig = lane & 3;
    const int base = blockIdx.x * MT;

    const uint32_t sW = sb + HDR;
    const uint32_t sA = sb + HDR + 2 * TB;

    if (tid < 128) {
        bias_s[tid] = bias[tid];
        if (EPI == 1) { w4_s[tid] = w4[tid]; red[tid] = 0.f; red[128 + tid] = 0.f; }
    }

    const int half = tid & 1, r = tid >> 1;

    {
        int i = base + r;
        int ridx;
        if (GATHER) ridx = (i < NVOX) ? nidx[(size_t)0 * NVOX + i] : NVOX;
        else        ridx = i;
        bool ok = (ridx < NVOX);
        const char* src = (const char*)(xin + (size_t)(ok ? ridx : 0) * CIN) + half * (CH2 * 16);
        uint32_t dst = sA + r * RB;
        #pragma unroll
        for (int c = 0; c < CH2; c++) {
            int cc = half * CH2 + c;
            cp16(dst + ((cc ^ (r & SWZ)) << 4), src + c * 16, ok ? 16u : 0u);
        }
    }
    cp_commit();

    float acc[2][2][8][4];
    #pragma unroll
    for (int tm = 0; tm < 2; tm++)
        #pragma unroll
        for (int a = 0; a < 2; a++)
            #pragma unroll
            for (int b = 0; b < 8; b++)
                #pragma unroll
                for (int q = 0; q < 4; q++) acc[tm][a][b][q] = 0.f;

    int buf = 0;
    for (int k = 0; k < NK; k++) {
        __syncthreads();
        {
            const __half* wsrc = half ? wlo : whi;
            const char* src = (const char*)(wsrc + ((size_t)k * 128 + r) * CIN);
            uint32_t dst = sW + half * TB + r * RB;
            #pragma unroll
            for (int c = 0; c < CHUNKS; c++)
                cp16(dst + ((c ^ (r & SWZ)) << 4), src + c * 16, 16u);
        }
        cp_commit();
        if (k + 1 < NK) {
            int i = base + r;
            int ridx;
            if (GATHER) ridx = (i < NVOX) ? nidx[(size_t)(k + 1) * NVOX + i] : NVOX;
            else        ridx = i;
            bool ok = (ridx < NVOX);
            const char* src = (const char*)(xin + (size_t)(ok ? ridx : 0) * CIN) + half * (CH2 * 16);
            uint32_t dst = sA + (buf ^ 1) * TB + r * RB;
            #pragma unroll
            for (int c = 0; c < CH2; c++) {
                int cc = half * CH2 + c;
                cp16(dst + ((cc ^ (r & SWZ)) << 4), src + c * 16, ok ? 16u : 0u);
            }
            cp_commit();
            cp_wait<1>();
        } else {
            cp_wait<0>();
        }
        __syncthreads();

        const uint32_t aT = sA + buf * TB;
        #pragma unroll
        for (int ks = 0; ks < KSTEPS; ks++) {
            const int kc0 = ks * 2;
            uint32_t am[2][4], bh[4][4], bl[4][4];
            #pragma unroll
            for (int mt = 0; mt < 2; mt++) {
                int row = wm * 32 + mt * 16 + (lane & 15);
                int c   = kc0 + (lane >> 4);
                ldsm4(am[mt], aT + row * RB + (((c ^ (row & SWZ))) << 4));
            }
            #pragma unroll
            for (int np = 0; np < 4; np++) {
                int n = wn * 64 + np * 16 + (lane & 7) + ((lane & 16) ? 8 : 0);
                int c = kc0 + ((lane >> 3) & 1);
                uint32_t ad = n * RB + (((c ^ (n & SWZ))) << 4);
                ldsm4(bh[np], sW + ad);
                ldsm4(bl[np], sW + TB + ad);
            }
            #pragma unroll
            for (int mt = 0; mt < 2; mt++)
                #pragma unroll
                for (int np = 0; np < 4; np++)
                    #pragma unroll
                    for (int s = 0; s < 2; s++) {
                        mma16816(acc[0][mt][np * 2 + s], am[mt], &bh[np][s * 2]);
                        mma16816(acc[1][mt][np * 2 + s], am[mt], &bl[np][s * 2]);
                    }
        }
        buf ^= 1;
    }
    __syncthreads();

    const float INV = 1.0f / LOSCALE;
    if (EPI == 0) {
        #pragma unroll
        for (int mt = 0; mt < 2; mt++) {
            int row0 = base + wm * 32 + mt * 16 + g;
            #pragma unroll
            for (int nt = 0; nt < 8; nt++) {
                int col = wn * 64 + nt * 8 + tig * 2;
                float v0 = silu_f(fmaf(acc[1][mt][nt][0], INV, acc[0][mt][nt][0]) + bias_s[col]);
                float v1 = silu_f(fmaf(acc[1][mt][nt][1], INV, acc[0][mt][nt][1]) + bias_s[col + 1]);
                float v2 = silu_f(fmaf(acc[1][mt][nt][2], INV, acc[0][mt][nt][2]) + bias_s[col]);
                float v3 = silu_f(fmaf(acc[1][mt][nt][3], INV, acc[0][mt][nt][3]) + bias_s[col + 1]);
                __half2 p0 = __floats2half2_rn(v0, v1);
                __half2 p1 = __floats2half2_rn(v2, v3);
                if (row0 < NVOX)
                    *(__half2*)(oh + (size_t)row0 * CH + col) = p0;
                if (row0 + 8 < NVOX)
                    *(__half2*)(oh + (size_t)(row0 + 8) * CH + col) = p1;
            }
        }
    } else {
        #pragma unroll
        for (int mt = 0; mt < 2; mt++) {
            float s0 = 0.f, s1 = 0.f;
            #pragma unroll
            for (int nt = 0; nt < 8; nt++) {
                int col = wn * 64 + nt * 8 + tig * 2;
                s0 += silu_f(fmaf(acc[1][mt][nt][0], INV, acc[0][mt][nt][0]) + bias_s[col])     * w4_s[col];
                s0 += silu_f(fmaf(acc[1][mt][nt][1], INV, acc[0][mt][nt][1]) + bias_s[col + 1]) * w4_s[col + 1];
                s1 += silu_f(fmaf(acc[1][mt][nt][2], INV, acc[0][mt][nt][2]) + bias_s[col])     * w4_s[col];
                s1 += silu_f(fmaf(acc[1][mt][nt][3], INV, acc[0][mt][nt][3]) + bias_s[col + 1]) * w4_s[col + 1];
            }
            s0 += __shfl_xor_sync(0xffffffffu, s0, 1);
            s0 += __shfl_xor_sync(0xffffffffu, s0, 2);
            s1 += __shfl_xor_sync(0xffffffffu, s1, 1);
            s1 += __shfl_xor_sync(0xffffffffu, s1, 2);
            if (tig == 0) {
                red[wn * 128 + wm * 32 + mt * 16 + g]     = s0;
                red[wn * 128 + wm * 32 + mt * 16 + g + 8] = s1;
            }
        }
        __syncthreads();
        if (tid < 128) {
            int i = base + tid;
            if (i < NVOX) ofl[i] = red[tid] + red[128 + tid] + b4[0];
        }
    }
}

// ---------------------------------------------------------------------------
extern "C" void kernel_launch(void* const* d_in, const int* in_sizes, int n_in,
                              void* d_out, int out_size)
{
    const float* feat = (const float*)d_in[0];
    const int*   t    = (const int*)  d_in[1];
    const int*   nidx = (const int*)  d_in[2];
    const float* W1   = (const float*)d_in[3];
    const float* b1   = (const float*)d_in[4];
    const float* W2   = (const float*)d_in[5];
    const float* b2   = (const float*)d_in[6];
    const float* W3   = (const float*)d_in[7];
    const float* b3   = (const float*)d_in[8];
    const float* W4   = (const float*)d_in[9];
    const float* b4   = (const float*)d_in[10];
    float* out = (float*)d_out;

    __half *px, *ph1, *ph2, *pw1h, *pw1l, *pw2h, *pw2l, *pw3h, *pw3l;
    cudaGetSymbolAddress((void**)&px,   g_x);
    cudaGetSymbolAddress((void**)&ph1,  g_h1);
    cudaGetSymbolAddress((void**)&ph2,  g_h2);
    cudaGetSymbolAddress((void**)&pw1h, g_w1_hi);
    cudaGetSymbolAddress((void**)&pw1l, g_w1_lo);
    cudaGetSymbolAddress((void**)&pw2h, g_w2_hi);
    cudaGetSymbolAddress((void**)&pw2l, g_w2_lo);
    cudaGetSymbolAddress((void**)&pw3h, g_w3_hi);
    cudaGetSymbolAddress((void**)&pw3l, g_w3_lo);

    // sparse kernels: 4096 hdr + acc(67584) + 2*W + 2*A
    const int smem_s1 = 4096 + 128 * ACCSTRIDE * 4 + 2 * (128 * 32)  + 2 * (128 * 32);
    const int smem_s2 = 4096 + 128 * ACCSTRIDE * 4 + 2 * (128 * 256) + 2 * (128 * 256);  // 202,752 B
    const int smem_l3 = 2048 + 4 * (128 * 128 * 2);                                       // 133,120 B
    cudaFuncSetAttribute(conv_sparse<16, 27>,
                         cudaFuncAttributeMaxDynamicSharedMemorySize, smem_s1);
    cudaFuncSetAttribute(conv_sparse<128, 27>,
                         cudaFuncAttributeMaxDynamicSharedMemorySize, smem_s2);
    cudaFuncSetAttribute(conv_mma<128, 1, false, 1>,
                         cudaFuncAttributeMaxDynamicSharedMemorySize, smem_l3);

    embed_k<<<(NVOX + 255) / 256, 256>>>(feat, t, px);
    prep_w1_k<<<(27 * 128 * 16  + 255) / 256, 256>>>(W1, pw1h, pw1l);
    prep_w2_k<<<(27 * 128 * 128 + 255) / 256, 256>>>(W2, pw2h, pw2l);
    prep_w3_k<<<(128 * 128      + 255) / 256, 256>>>(W3, pw3h, pw3l);

    conv_sparse<16, 27><<<NT, NTHREADS, smem_s1>>>(px,  nidx, pw1h, pw1l, b1, ph1);
    conv_sparse<128, 27><<<NT, NTHREADS, smem_s2>>>(ph1, nidx, pw2h, pw2l, b2, ph2);
    conv_mma<128, 1, false, 1><<<NT, NTHREADS, smem_l3>>>(
        ph2, nullptr, pw3h, pw3l, b3, W4, b4, nullptr, out);
}